// round 1
// baseline (speedup 1.0000x reference)
#include <cuda_runtime.h>
#include <math.h>

// Problem constants (fixed shapes per reference)
constexpr int BATCH = 8192;
constexpr int INPUT = 4096;
constexpr int HIDDEN = 4096;
constexpr int CLASSES = 1000;

// Scratch (alloc-free: __device__ globals)
__device__ float g_hidden[(size_t)BATCH * HIDDEN];   // 134 MB
__device__ float g_logits[(size_t)BATCH * CLASSES];  // 33 MB

// ---------------------------------------------------------------------------
// NT GEMM: C[m,n] = sum_k A[m,k] * B[n,k] + bias[n], optional ReLU.
// A: [M,K] row-major, B: [N,K] row-major (both K-contiguous).
// 128x128 block tile, BK=8, 8x8 per-thread micro-tile, 256 threads.
// M assumed multiple of 128, K multiple of 8. N guarded if NGUARD.
// ---------------------------------------------------------------------------
template <bool RELU, bool NGUARD>
__global__ __launch_bounds__(256, 2)
void gemm_nt_kernel(const float* __restrict__ A,
                    const float* __restrict__ Bm,
                    const float* __restrict__ bias,
                    float* __restrict__ C,
                    int M, int N, int K) {
    constexpr int BM = 128, BN = 128, BK = 8, TM = 8, TN = 8;

    __shared__ float As[BK][BM];
    __shared__ float Bs[BK][BN];

    const int tid = threadIdx.x;
    const int brow = blockIdx.y * BM;
    const int bcol = blockIdx.x * BN;

    // Loader mapping: 256 threads, each loads one float4 of A and one of B.
    const int loadRow = tid >> 1;        // 0..127
    const int loadK   = (tid & 1) * 4;   // 0 or 4

    const float* Ag = A + (size_t)(brow + loadRow) * K + loadK;
    const int bRowG = bcol + loadRow;
    const bool bValid = (!NGUARD) || (bRowG < N);
    const float* Bg = Bm + (size_t)(bValid ? bRowG : 0) * K + loadK;

    // Compute mapping: 16x16 thread grid, each owns 8x8 outputs.
    const int ty = tid >> 4;  // 0..15
    const int tx = tid & 15;  // 0..15

    float acc[TM][TN];
    #pragma unroll
    for (int i = 0; i < TM; i++)
        #pragma unroll
        for (int j = 0; j < TN; j++) acc[i][j] = 0.0f;

    float4 aReg = *reinterpret_cast<const float4*>(Ag);
    float4 bReg = bValid ? *reinterpret_cast<const float4*>(Bg)
                         : make_float4(0.f, 0.f, 0.f, 0.f);

    for (int k0 = 0; k0 < K; k0 += BK) {
        // Store current tile (transposed: k-major rows)
        As[loadK + 0][loadRow] = aReg.x;
        As[loadK + 1][loadRow] = aReg.y;
        As[loadK + 2][loadRow] = aReg.z;
        As[loadK + 3][loadRow] = aReg.w;
        Bs[loadK + 0][loadRow] = bReg.x;
        Bs[loadK + 1][loadRow] = bReg.y;
        Bs[loadK + 2][loadRow] = bReg.z;
        Bs[loadK + 3][loadRow] = bReg.w;
        __syncthreads();

        const bool more = (k0 + BK) < K;
        if (more) {
            aReg = *reinterpret_cast<const float4*>(Ag + k0 + BK);
            if (bValid)
                bReg = *reinterpret_cast<const float4*>(Bg + k0 + BK);
        }

        #pragma unroll
        for (int kk = 0; kk < BK; kk++) {
            float aFrag[TM], bFrag[TN];
            const float4* aRow = reinterpret_cast<const float4*>(&As[kk][ty * TM]);
            const float4* bRow = reinterpret_cast<const float4*>(&Bs[kk][tx * TN]);
            float4 a0 = aRow[0], a1 = aRow[1];
            float4 b0 = bRow[0], b1 = bRow[1];
            aFrag[0] = a0.x; aFrag[1] = a0.y; aFrag[2] = a0.z; aFrag[3] = a0.w;
            aFrag[4] = a1.x; aFrag[5] = a1.y; aFrag[6] = a1.z; aFrag[7] = a1.w;
            bFrag[0] = b0.x; bFrag[1] = b0.y; bFrag[2] = b0.z; bFrag[3] = b0.w;
            bFrag[4] = b1.x; bFrag[5] = b1.y; bFrag[6] = b1.z; bFrag[7] = b1.w;
            #pragma unroll
            for (int i = 0; i < TM; i++)
                #pragma unroll
                for (int j = 0; j < TN; j++)
                    acc[i][j] = fmaf(aFrag[i], bFrag[j], acc[i][j]);
        }

        if (!more) break;
        __syncthreads();
    }

    // Epilogue: bias (+ReLU), guarded writes along N.
    #pragma unroll
    for (int i = 0; i < TM; i++) {
        const int r = brow + ty * TM + i;
        float* Cp = C + (size_t)r * N;
        #pragma unroll
        for (int j = 0; j < TN; j++) {
            const int c = bcol + tx * TN + j;
            if (!NGUARD || c < N) {
                float v = acc[i][j] + bias[c];
                if (RELU) v = fmaxf(v, 0.0f);
                Cp[c] = v;
            }
        }
    }
}

// ---------------------------------------------------------------------------
// Row softmax over CLASSES columns. One block (256 threads) per row.
// ---------------------------------------------------------------------------
__inline__ __device__ float warpReduceMax(float v) {
    #pragma unroll
    for (int o = 16; o > 0; o >>= 1)
        v = fmaxf(v, __shfl_xor_sync(0xffffffffu, v, o));
    return v;
}
__inline__ __device__ float warpReduceSum(float v) {
    #pragma unroll
    for (int o = 16; o > 0; o >>= 1)
        v += __shfl_xor_sync(0xffffffffu, v, o);
    return v;
}

__global__ __launch_bounds__(256)
void softmax_kernel(const float* __restrict__ logits, float* __restrict__ out) {
    const int row = blockIdx.x;
    const float* lp = logits + (size_t)row * CLASSES;
    float* op = out + (size_t)row * CLASSES;

    const int tid = threadIdx.x;
    const int lane = tid & 31;
    const int warp = tid >> 5;
    __shared__ float red[8];

    // Each thread handles up to 4 elements (256*4 = 1024 >= 1000).
    float v[4];
    int idx[4];
    int cnt = 0;
    for (int i = tid; i < CLASSES; i += 256) {
        v[cnt] = lp[i];
        idx[cnt] = i;
        cnt++;
    }

    float m = -INFINITY;
    for (int t = 0; t < cnt; t++) m = fmaxf(m, v[t]);
    m = warpReduceMax(m);
    if (lane == 0) red[warp] = m;
    __syncthreads();
    m = (lane < 8) ? red[lane] : -INFINITY;
    m = warpReduceMax(m);
    m = __shfl_sync(0xffffffffu, m, 0);

    float s = 0.0f;
    for (int t = 0; t < cnt; t++) {
        v[t] = __expf(v[t] - m);
        s += v[t];
    }
    s = warpReduceSum(s);
    __syncthreads();
    if (lane == 0) red[warp] = s;
    __syncthreads();
    s = (lane < 8) ? red[lane] : 0.0f;
    s = warpReduceSum(s);
    s = __shfl_sync(0xffffffffu, s, 0);

    const float inv = 1.0f / s;
    for (int t = 0; t < cnt; t++) op[idx[t]] = v[t] * inv;
}

// ---------------------------------------------------------------------------
// Launch
// ---------------------------------------------------------------------------
extern "C" void kernel_launch(void* const* d_in, const int* in_sizes, int n_in,
                              void* d_out, int out_size) {
    const float* x   = (const float*)d_in[0];  // [8192, 4096]
    const float* w1  = (const float*)d_in[1];  // [4096, 4096]
    const float* b1  = (const float*)d_in[2];  // [4096]
    const float* w2  = (const float*)d_in[3];  // [1000, 4096]
    const float* b2  = (const float*)d_in[4];  // [1000]
    float* out = (float*)d_out;                // [8192, 1000]

    float* hidden = nullptr;
    float* logits = nullptr;
    cudaGetSymbolAddress((void**)&hidden, g_hidden);
    cudaGetSymbolAddress((void**)&logits, g_logits);

    // GEMM1: hidden = relu(x @ w1^T + b1)   [8192, 4096]
    {
        dim3 grid(HIDDEN / 128, BATCH / 128);
        gemm_nt_kernel<true, false><<<grid, 256>>>(x, w1, b1, hidden,
                                                   BATCH, HIDDEN, INPUT);
    }
    // GEMM2: logits = hidden @ w2^T + b2    [8192, 1000]
    {
        dim3 grid((CLASSES + 127) / 128, BATCH / 128);
        gemm_nt_kernel<false, true><<<grid, 256>>>(hidden, w2, b2, logits,
                                                   BATCH, CLASSES, HIDDEN);
    }
    // Softmax rows
    softmax_kernel<<<BATCH, 256>>>(logits, out);
}

// round 4
// speedup vs baseline: 1.3789x; 1.3789x over previous
#include <cuda_runtime.h>
#include <cuda_bf16.h>
#include <math.h>
#include <stdint.h>

// ---------------------------------------------------------------------------
// Problem constants
// ---------------------------------------------------------------------------
constexpr int BATCH = 8192, INPUT = 4096, HIDDEN = 4096, CLASSES = 1000;
constexpr int NPAD = 1024;
constexpr int KDIM = 4096;
constexpr int BM = 128, BN = 128, BK = 32;
constexpr int NITER = KDIM / BK;           // 128
constexpr int STRIDE = 80;                 // padded smem row bytes (64 data + 16 pad)
constexpr int TILE_B = 128 * STRIDE;       // 10240 bytes per tile
constexpr int STAGE_B = 6 * TILE_B;        // 61440 (A0,B0,A1,B1,A2,B2)
constexpr int NSTAGES = 3;
constexpr int DYN_SMEM = NSTAGES * STAGE_B;  // 184320

// ---------------------------------------------------------------------------
// Scratch (__device__ globals; allocation-free)
// ---------------------------------------------------------------------------
__device__ __align__(1024) __nv_bfloat16 g_x_s[3][(size_t)BATCH * INPUT];
__device__ __align__(1024) __nv_bfloat16 g_w1_s[3][(size_t)HIDDEN * INPUT];
__device__ __align__(1024) __nv_bfloat16 g_w2_s[3][(size_t)NPAD * INPUT];
__device__ __align__(1024) __nv_bfloat16 g_h_s[3][(size_t)BATCH * HIDDEN];
__device__ __align__(1024) float g_logits[(size_t)BATCH * NPAD];

// ---------------------------------------------------------------------------
// PTX helpers (sm_80-level only: cp.async, ldmatrix, mma.sync)
// ---------------------------------------------------------------------------
__device__ __forceinline__ uint32_t smem_u32(const void* p) {
    uint32_t a;
    asm("{ .reg .u64 t; cvta.to.shared.u64 t, %1; cvt.u32.u64 %0, t; }"
        : "=r"(a) : "l"(p));
    return a;
}
__device__ __forceinline__ void cp_async16(uint32_t dst, const void* src) {
    asm volatile("cp.async.cg.shared.global [%0], [%1], 16;"
                 :: "r"(dst), "l"(src) : "memory");
}
__device__ __forceinline__ void cp_commit() {
    asm volatile("cp.async.commit_group;" ::: "memory");
}
__device__ __forceinline__ void cp_wait1() {
    asm volatile("cp.async.wait_group 1;" ::: "memory");
}
__device__ __forceinline__ void ldmatrix_x4(uint32_t& r0, uint32_t& r1,
                                            uint32_t& r2, uint32_t& r3, uint32_t a) {
    asm volatile("ldmatrix.sync.aligned.m8n8.x4.shared.b16 {%0,%1,%2,%3}, [%4];"
                 : "=r"(r0), "=r"(r1), "=r"(r2), "=r"(r3) : "r"(a));
}
__device__ __forceinline__ void mma_bf16(float* d, const uint32_t* a, const uint32_t* b) {
    asm volatile(
        "mma.sync.aligned.m16n8k16.row.col.f32.bf16.bf16.f32 "
        "{%0,%1,%2,%3}, {%4,%5,%6,%7}, {%8,%9}, {%0,%1,%2,%3};"
        : "+f"(d[0]), "+f"(d[1]), "+f"(d[2]), "+f"(d[3])
        : "r"(a[0]), "r"(a[1]), "r"(a[2]), "r"(a[3]), "r"(b[0]), "r"(b[1]));
}

__device__ __forceinline__ uint32_t pack_bf16(__nv_bfloat16 a, __nv_bfloat16 b) {
    __nv_bfloat162 t{a, b};
    uint32_t r;
    memcpy(&r, &t, 4);
    return r;
}
__device__ __forceinline__ void split3(float v, __nv_bfloat16& h,
                                       __nv_bfloat16& m, __nv_bfloat16& l) {
    h = __float2bfloat16(v);
    float r1 = v - __bfloat162float(h);
    m = __float2bfloat16(r1);
    float r2 = r1 - __bfloat162float(m);
    l = __float2bfloat16(r2);
}

// ---------------------------------------------------------------------------
// Split kernels (fp32 -> 3x bf16 components)
// ---------------------------------------------------------------------------
__global__ __launch_bounds__(256)
void split3_kernel(const float4* __restrict__ in, int n4,
                   __nv_bfloat16* __restrict__ h, __nv_bfloat16* __restrict__ m,
                   __nv_bfloat16* __restrict__ l) {
    int i = blockIdx.x * blockDim.x + threadIdx.x;
    if (i >= n4) return;
    float4 v = in[i];
    __nv_bfloat16 h0, h1, h2, h3, m0, m1, m2, m3, l0, l1, l2, l3;
    split3(v.x, h0, m0, l0);
    split3(v.y, h1, m1, l1);
    split3(v.z, h2, m2, l2);
    split3(v.w, h3, m3, l3);
    ((uint2*)h)[i] = make_uint2(pack_bf16(h0, h1), pack_bf16(h2, h3));
    ((uint2*)m)[i] = make_uint2(pack_bf16(m0, m1), pack_bf16(m2, m3));
    ((uint2*)l)[i] = make_uint2(pack_bf16(l0, l1), pack_bf16(l2, l3));
}

__global__ __launch_bounds__(256)
void split3_pad_kernel(const float4* __restrict__ in, int n4_total,
                       __nv_bfloat16* __restrict__ h, __nv_bfloat16* __restrict__ m,
                       __nv_bfloat16* __restrict__ l) {
    int i = blockIdx.x * blockDim.x + threadIdx.x;
    if (i >= n4_total) return;
    int row = i >> 10;  // INPUT/4 = 1024 float4 per row
    float4 v = (row < CLASSES) ? in[i] : make_float4(0.f, 0.f, 0.f, 0.f);
    __nv_bfloat16 h0, h1, h2, h3, m0, m1, m2, m3, l0, l1, l2, l3;
    split3(v.x, h0, m0, l0);
    split3(v.y, h1, m1, l1);
    split3(v.z, h2, m2, l2);
    split3(v.w, h3, m3, l3);
    ((uint2*)h)[i] = make_uint2(pack_bf16(h0, h1), pack_bf16(h2, h3));
    ((uint2*)m)[i] = make_uint2(pack_bf16(m0, m1), pack_bf16(m2, m3));
    ((uint2*)l)[i] = make_uint2(pack_bf16(l0, l1), pack_bf16(l2, l3));
}

// ---------------------------------------------------------------------------
// Pipelined mma.sync bf16 GEMM, 6-product split, DUAL accumulators:
//   acc  <- hi*hi                      (fp32-equivalent rounding)
//   acc2 <- hi*mid + mid*hi + hi*lo + mid*mid + lo*hi   (small-magnitude acc)
// C = acc + acc2.
// MODE 0: out = relu(C + bias), re-split to 3 bf16 arrays (ld = HIDDEN)
// MODE 1: out = C + bias (fp32, ld = NPAD, bias guarded to biasN)
// ---------------------------------------------------------------------------
template <int MODE>
__global__ __launch_bounds__(256, 1)
void gemm_kernel(const __nv_bfloat16* __restrict__ A0,
                 const __nv_bfloat16* __restrict__ A1,
                 const __nv_bfloat16* __restrict__ A2,
                 const __nv_bfloat16* __restrict__ B0,
                 const __nv_bfloat16* __restrict__ B1,
                 const __nv_bfloat16* __restrict__ B2,
                 const float* __restrict__ bias, int biasN,
                 __nv_bfloat16* __restrict__ o_hi,
                 __nv_bfloat16* __restrict__ o_mi,
                 __nv_bfloat16* __restrict__ o_lo,
                 float* __restrict__ o_f32) {
    extern __shared__ __align__(128) char smem[];
    const uint32_t smem_u = smem_u32(smem);

    const int tid = threadIdx.x;
    const int lane = tid & 31;
    const int wid = tid >> 5;
    const int warpRow = wid >> 2;   // 0..1 -> 64 rows each
    const int warpCol = wid & 3;    // 0..3 -> 32 cols each
    const int blockM = blockIdx.y * BM;
    const int blockN = blockIdx.x * BN;

    const char* Ag[3] = {(const char*)A0, (const char*)A1, (const char*)A2};
    const char* Bg[3] = {(const char*)B0, (const char*)B1, (const char*)B2};
    constexpr size_t K2 = (size_t)KDIM * 2;

    // ---- stage loader: 3072 16B chunks, 12 per thread ----
    auto load_stage = [&](int buf, int k0) {
        const uint32_t sbase = smem_u + buf * STAGE_B;
        #pragma unroll
        for (int i = 0; i < 12; i++) {
            int L = tid + i * 256;
            int mc = L >> 9;          // 0..5: (comp<<1)|mat
            int c = L & 511;
            int row = c >> 2, ch = c & 3;
            int comp = mc >> 1, mat = mc & 1;
            const char* g;
            if (mat == 0)
                g = Ag[comp] + (size_t)(blockM + row) * K2 + (size_t)k0 * 2 + ch * 16;
            else
                g = Bg[comp] + (size_t)(blockN + row) * K2 + (size_t)k0 * 2 + ch * 16;
            cp_async16(sbase + mc * TILE_B + row * STRIDE + ch * 16, g);
        }
        cp_commit();
    };

    float acc[4][4][4];   // main: hi*hi
    float acc2[4][4][4];  // corrections
    #pragma unroll
    for (int mt = 0; mt < 4; mt++)
        #pragma unroll
        for (int nt = 0; nt < 4; nt++)
            #pragma unroll
            for (int e = 0; e < 4; e++) { acc[mt][nt][e] = 0.0f; acc2[mt][nt][e] = 0.0f; }

    // ldmatrix per-lane address components
    const int rA = ((lane >> 3) & 1) * 8 + (lane & 7);
    const int cA = (lane >> 4);          // 0/1 -> k-half chunk
    const int rB = (lane >> 4) * 8 + (lane & 7);
    const int cB = (lane >> 3) & 1;

    load_stage(0, 0);
    load_stage(1, BK);

    for (int it = 0; it < NITER; it++) {
        const int buf = it % NSTAGES;
        cp_wait1();
        __syncthreads();

        if (it + 2 < NITER) load_stage((it + 2) % NSTAGES, (it + 2) * BK);
        else cp_commit();

        const uint32_t stage = smem_u + buf * STAGE_B;
        #pragma unroll
        for (int kh = 0; kh < 2; kh++) {
            uint32_t aF[3][4][4];
            uint32_t bF[3][4][2];
            #pragma unroll
            for (int t = 0; t < 3; t++) {
                const uint32_t Abase = stage + (2 * t) * TILE_B;
                const uint32_t Bbase = stage + (2 * t + 1) * TILE_B;
                #pragma unroll
                for (int mt = 0; mt < 4; mt++) {
                    uint32_t addr = Abase + (warpRow * 64 + mt * 16 + rA) * STRIDE +
                                    (kh * 2 + cA) * 16;
                    ldmatrix_x4(aF[t][mt][0], aF[t][mt][1], aF[t][mt][2], aF[t][mt][3], addr);
                }
                #pragma unroll
                for (int pr = 0; pr < 2; pr++) {
                    uint32_t addr = Bbase + (warpCol * 32 + pr * 16 + rB) * STRIDE +
                                    (kh * 2 + cB) * 16;
                    uint32_t r0, r1, r2, r3;
                    ldmatrix_x4(r0, r1, r2, r3, addr);
                    bF[t][pr * 2 + 0][0] = r0; bF[t][pr * 2 + 0][1] = r1;
                    bF[t][pr * 2 + 1][0] = r2; bF[t][pr * 2 + 1][1] = r3;
                }
            }
            // main product -> acc
            #pragma unroll
            for (int mt = 0; mt < 4; mt++)
                #pragma unroll
                for (int nt = 0; nt < 4; nt++)
                    mma_bf16(acc[mt][nt], aF[0][mt], bF[0][nt]);
            // 5 correction products -> acc2
            const int pa[5] = {0, 1, 0, 1, 2};
            const int pb[5] = {1, 0, 2, 1, 0};
            #pragma unroll
            for (int p = 0; p < 5; p++) {
                #pragma unroll
                for (int mt = 0; mt < 4; mt++)
                    #pragma unroll
                    for (int nt = 0; nt < 4; nt++)
                        mma_bf16(acc2[mt][nt], aF[pa[p]][mt], bF[pb[p]][nt]);
            }
        }
        __syncthreads();
    }

    // ---- epilogue ----
    const int gr = lane >> 2;         // row within 8
    const int cc = (lane & 3) * 2;    // col pair

    #pragma unroll
    for (int mt = 0; mt < 4; mt++) {
        #pragma unroll
        for (int nt = 0; nt < 4; nt++) {
            float d[4];
            #pragma unroll
            for (int e = 0; e < 4; e++) d[e] = acc[mt][nt][e] + acc2[mt][nt][e];
            const int col = blockN + warpCol * 32 + nt * 8 + cc;
            const int row0 = blockM + warpRow * 64 + mt * 16 + gr;
            float bv0, bv1;
            if (MODE == 0) {
                bv0 = bias[col];
                bv1 = bias[col + 1];
            } else {
                bv0 = (col < biasN) ? bias[col] : 0.0f;
                bv1 = (col + 1 < biasN) ? bias[col + 1] : 0.0f;
            }
            if (MODE == 0) {
                #pragma unroll
                for (int h = 0; h < 2; h++) {
                    const int row = row0 + h * 8;
                    float v0 = fmaxf(d[2 * h + 0] + bv0, 0.0f);
                    float v1 = fmaxf(d[2 * h + 1] + bv1, 0.0f);
                    __nv_bfloat16 h0, m0, l0, h1, m1, l1;
                    split3(v0, h0, m0, l0);
                    split3(v1, h1, m1, l1);
                    size_t off = (size_t)row * HIDDEN + col;
                    *(uint32_t*)(o_hi + off) = pack_bf16(h0, h1);
                    *(uint32_t*)(o_mi + off) = pack_bf16(m0, m1);
                    *(uint32_t*)(o_lo + off) = pack_bf16(l0, l1);
                }
            } else {
                #pragma unroll
                for (int h = 0; h < 2; h++) {
                    const int row = row0 + h * 8;
                    float2 v;
                    v.x = d[2 * h + 0] + bv0;
                    v.y = d[2 * h + 1] + bv1;
                    *(float2*)(o_f32 + (size_t)row * NPAD + col) = v;
                }
            }
        }
    }
}

// ---------------------------------------------------------------------------
// Row softmax (reads NPAD-strided logits, first CLASSES cols)
// ---------------------------------------------------------------------------
__inline__ __device__ float warpMax(float v) {
    #pragma unroll
    for (int o = 16; o > 0; o >>= 1) v = fmaxf(v, __shfl_xor_sync(0xffffffffu, v, o));
    return v;
}
__inline__ __device__ float warpSum(float v) {
    #pragma unroll
    for (int o = 16; o > 0; o >>= 1) v += __shfl_xor_sync(0xffffffffu, v, o);
    return v;
}

__global__ __launch_bounds__(256)
void softmax_kernel(const float* __restrict__ logits, float* __restrict__ out) {
    const int row = blockIdx.x;
    const float* lp = logits + (size_t)row * NPAD;
    float* op = out + (size_t)row * CLASSES;

    const int tid = threadIdx.x, lane = tid & 31, warp = tid >> 5;
    __shared__ float red[8];

    float v[4];
    int idx[4], cnt = 0;
    for (int i = tid; i < CLASSES; i += 256) { v[cnt] = lp[i]; idx[cnt] = i; cnt++; }

    float m = -INFINITY;
    for (int t = 0; t < cnt; t++) m = fmaxf(m, v[t]);
    m = warpMax(m);
    if (lane == 0) red[warp] = m;
    __syncthreads();
    m = (lane < 8) ? red[lane] : -INFINITY;
    m = warpMax(m);
    m = __shfl_sync(0xffffffffu, m, 0);

    float s = 0.0f;
    for (int t = 0; t < cnt; t++) { v[t] = __expf(v[t] - m); s += v[t]; }
    s = warpSum(s);
    __syncthreads();
    if (lane == 0) red[warp] = s;
    __syncthreads();
    s = (lane < 8) ? red[lane] : 0.0f;
    s = warpSum(s);
    s = __shfl_sync(0xffffffffu, s, 0);

    const float inv = 1.0f / s;
    for (int t = 0; t < cnt; t++) op[idx[t]] = v[t] * inv;
}

// ---------------------------------------------------------------------------
// Host launch
// ---------------------------------------------------------------------------
extern "C" void kernel_launch(void* const* d_in, const int* in_sizes, int n_in,
                              void* d_out, int out_size) {
    const float* x  = (const float*)d_in[0];
    const float* w1 = (const float*)d_in[1];
    const float* b1 = (const float*)d_in[2];
    const float* w2 = (const float*)d_in[3];
    const float* b2 = (const float*)d_in[4];
    float* out = (float*)d_out;

    __nv_bfloat16 *xs, *w1s, *w2s, *hs;
    float* logits;
    cudaGetSymbolAddress((void**)&xs,  g_x_s);
    cudaGetSymbolAddress((void**)&w1s, g_w1_s);
    cudaGetSymbolAddress((void**)&w2s, g_w2_s);
    cudaGetSymbolAddress((void**)&hs,  g_h_s);
    cudaGetSymbolAddress((void**)&logits, g_logits);

    const size_t XN  = (size_t)BATCH * INPUT;
    const size_t W1N = (size_t)HIDDEN * INPUT;
    const size_t W2N = (size_t)NPAD * INPUT;
    const size_t HN  = (size_t)BATCH * HIDDEN;

    __nv_bfloat16* x_c[3]  = {xs, xs + XN, xs + 2 * XN};
    __nv_bfloat16* w1_c[3] = {w1s, w1s + W1N, w1s + 2 * W1N};
    __nv_bfloat16* w2_c[3] = {w2s, w2s + W2N, w2s + 2 * W2N};
    __nv_bfloat16* h_c[3]  = {hs, hs + HN, hs + 2 * HN};

    {
        int n4 = (int)(XN / 4);
        split3_kernel<<<(n4 + 255) / 256, 256>>>((const float4*)x, n4, x_c[0], x_c[1], x_c[2]);
    }
    {
        int n4 = (int)(W1N / 4);
        split3_kernel<<<(n4 + 255) / 256, 256>>>((const float4*)w1, n4, w1_c[0], w1_c[1], w1_c[2]);
    }
    {
        int n4 = (int)(W2N / 4);
        split3_pad_kernel<<<(n4 + 255) / 256, 256>>>((const float4*)w2, n4, w2_c[0], w2_c[1], w2_c[2]);
    }

    cudaFuncSetAttribute(gemm_kernel<0>, cudaFuncAttributeMaxDynamicSharedMemorySize, DYN_SMEM);
    cudaFuncSetAttribute(gemm_kernel<1>, cudaFuncAttributeMaxDynamicSharedMemorySize, DYN_SMEM);

    // GEMM1: hidden = relu(x @ w1^T + b1), re-split into 3 bf16 components
    {
        dim3 grid(HIDDEN / BN, BATCH / BM);
        gemm_kernel<0><<<grid, 256, DYN_SMEM>>>(
            x_c[0], x_c[1], x_c[2], w1_c[0], w1_c[1], w1_c[2],
            b1, HIDDEN, h_c[0], h_c[1], h_c[2], nullptr);
    }
    // GEMM2: logits = hidden @ w2^T + b2 (fp32, NPAD-wide scratch)
    {
        dim3 grid(NPAD / BN, BATCH / BM);
        gemm_kernel<1><<<grid, 256, DYN_SMEM>>>(
            h_c[0], h_c[1], h_c[2], w2_c[0], w2_c[1], w2_c[2],
            b2, CLASSES, nullptr, nullptr, nullptr, logits);
    }
    softmax_kernel<<<BATCH, 256>>>(logits, out);
}

// round 5
// speedup vs baseline: 1.5370x; 1.1147x over previous
#include <cuda_runtime.h>
#include <cuda_bf16.h>
#include <math.h>
#include <stdint.h>

// ---------------------------------------------------------------------------
// Problem constants
// ---------------------------------------------------------------------------
constexpr int BATCH = 8192, INPUT = 4096, HIDDEN = 4096, CLASSES = 1000;
constexpr int NPAD = 1024;
constexpr int KDIM = 4096;
constexpr int BM = 128, BN = 128, BK = 64;
constexpr int NITER = KDIM / BK;           // 64
constexpr int STRIDE = 144;                // padded smem row bytes (128 data + 16 pad)
constexpr int TILE_B = 128 * STRIDE;       // 18432 bytes per tile
constexpr int STAGE_B = 6 * TILE_B;        // 110592 (A0,B0,A1,B1,A2,B2)
constexpr int NSTAGES = 2;
constexpr int DYN_SMEM = NSTAGES * STAGE_B;  // 221184

// ---------------------------------------------------------------------------
// Scratch (__device__ globals; allocation-free)
// ---------------------------------------------------------------------------
__device__ __align__(1024) __nv_bfloat16 g_x_s[3][(size_t)BATCH * INPUT];
__device__ __align__(1024) __nv_bfloat16 g_w1_s[3][(size_t)HIDDEN * INPUT];
__device__ __align__(1024) __nv_bfloat16 g_w2_s[3][(size_t)NPAD * INPUT];
__device__ __align__(1024) __nv_bfloat16 g_h_s[3][(size_t)BATCH * HIDDEN];
__device__ __align__(1024) float g_logits[(size_t)BATCH * NPAD];

// ---------------------------------------------------------------------------
// PTX helpers (sm_80-level only: cp.async, ldmatrix, mma.sync)
// ---------------------------------------------------------------------------
__device__ __forceinline__ uint32_t smem_u32(const void* p) {
    uint32_t a;
    asm("{ .reg .u64 t; cvta.to.shared.u64 t, %1; cvt.u32.u64 %0, t; }"
        : "=r"(a) : "l"(p));
    return a;
}
__device__ __forceinline__ void cp_async16(uint32_t dst, const void* src) {
    asm volatile("cp.async.cg.shared.global [%0], [%1], 16;"
                 :: "r"(dst), "l"(src) : "memory");
}
__device__ __forceinline__ void cp_commit() {
    asm volatile("cp.async.commit_group;" ::: "memory");
}
__device__ __forceinline__ void cp_wait0() {
    asm volatile("cp.async.wait_group 0;" ::: "memory");
}
__device__ __forceinline__ void ldmatrix_x4(uint32_t& r0, uint32_t& r1,
                                            uint32_t& r2, uint32_t& r3, uint32_t a) {
    asm volatile("ldmatrix.sync.aligned.m8n8.x4.shared.b16 {%0,%1,%2,%3}, [%4];"
                 : "=r"(r0), "=r"(r1), "=r"(r2), "=r"(r3) : "r"(a));
}
__device__ __forceinline__ void mma_bf16(float* d, const uint32_t* a, const uint32_t* b) {
    asm volatile(
        "mma.sync.aligned.m16n8k16.row.col.f32.bf16.bf16.f32 "
        "{%0,%1,%2,%3}, {%4,%5,%6,%7}, {%8,%9}, {%0,%1,%2,%3};"
        : "+f"(d[0]), "+f"(d[1]), "+f"(d[2]), "+f"(d[3])
        : "r"(a[0]), "r"(a[1]), "r"(a[2]), "r"(a[3]), "r"(b[0]), "r"(b[1]));
}

__device__ __forceinline__ uint32_t pack_bf16(__nv_bfloat16 a, __nv_bfloat16 b) {
    __nv_bfloat162 t{a, b};
    uint32_t r;
    memcpy(&r, &t, 4);
    return r;
}
__device__ __forceinline__ void split3(float v, __nv_bfloat16& h,
                                       __nv_bfloat16& m, __nv_bfloat16& l) {
    h = __float2bfloat16(v);
    float r1 = v - __bfloat162float(h);
    m = __float2bfloat16(r1);
    float r2 = r1 - __bfloat162float(m);
    l = __float2bfloat16(r2);
}

// ---------------------------------------------------------------------------
// Split kernels (fp32 -> 3x bf16 components)
// ---------------------------------------------------------------------------
__global__ __launch_bounds__(256)
void split3_kernel(const float4* __restrict__ in, int n4,
                   __nv_bfloat16* __restrict__ h, __nv_bfloat16* __restrict__ m,
                   __nv_bfloat16* __restrict__ l) {
    int i = blockIdx.x * blockDim.x + threadIdx.x;
    if (i >= n4) return;
    float4 v = in[i];
    __nv_bfloat16 h0, h1, h2, h3, m0, m1, m2, m3, l0, l1, l2, l3;
    split3(v.x, h0, m0, l0);
    split3(v.y, h1, m1, l1);
    split3(v.z, h2, m2, l2);
    split3(v.w, h3, m3, l3);
    ((uint2*)h)[i] = make_uint2(pack_bf16(h0, h1), pack_bf16(h2, h3));
    ((uint2*)m)[i] = make_uint2(pack_bf16(m0, m1), pack_bf16(m2, m3));
    ((uint2*)l)[i] = make_uint2(pack_bf16(l0, l1), pack_bf16(l2, l3));
}

__global__ __launch_bounds__(256)
void split3_pad_kernel(const float4* __restrict__ in, int n4_total,
                       __nv_bfloat16* __restrict__ h, __nv_bfloat16* __restrict__ m,
                       __nv_bfloat16* __restrict__ l) {
    int i = blockIdx.x * blockDim.x + threadIdx.x;
    if (i >= n4_total) return;
    int row = i >> 10;  // INPUT/4 = 1024 float4 per row
    float4 v = (row < CLASSES) ? in[i] : make_float4(0.f, 0.f, 0.f, 0.f);
    __nv_bfloat16 h0, h1, h2, h3, m0, m1, m2, m3, l0, l1, l2, l3;
    split3(v.x, h0, m0, l0);
    split3(v.y, h1, m1, l1);
    split3(v.z, h2, m2, l2);
    split3(v.w, h3, m3, l3);
    ((uint2*)h)[i] = make_uint2(pack_bf16(h0, h1), pack_bf16(h2, h3));
    ((uint2*)m)[i] = make_uint2(pack_bf16(m0, m1), pack_bf16(m2, m3));
    ((uint2*)l)[i] = make_uint2(pack_bf16(l0, l1), pack_bf16(l2, l3));
}

// ---------------------------------------------------------------------------
// Pipelined mma.sync bf16 GEMM, 6-product split, DUAL accumulators:
//   acc  <- hi*hi ; acc2 <- hi*mid + mid*hi + hi*lo + mid*mid + lo*hi
// 2-stage, BK=64, single barrier per k-iter, loads issued at iter start.
// MODE 0: out = relu(C + bias), re-split to 3 bf16 arrays (ld = HIDDEN)
// MODE 1: out = C + bias (fp32, ld = NPAD, bias guarded to biasN)
// ---------------------------------------------------------------------------
template <int MODE>
__global__ __launch_bounds__(256, 1)
void gemm_kernel(const __nv_bfloat16* __restrict__ A0,
                 const __nv_bfloat16* __restrict__ A1,
                 const __nv_bfloat16* __restrict__ A2,
                 const __nv_bfloat16* __restrict__ B0,
                 const __nv_bfloat16* __restrict__ B1,
                 const __nv_bfloat16* __restrict__ B2,
                 const float* __restrict__ bias, int biasN,
                 __nv_bfloat16* __restrict__ o_hi,
                 __nv_bfloat16* __restrict__ o_mi,
                 __nv_bfloat16* __restrict__ o_lo,
                 float* __restrict__ o_f32) {
    extern __shared__ __align__(128) char smem[];
    const uint32_t smem_u = smem_u32(smem);

    const int tid = threadIdx.x;
    const int lane = tid & 31;
    const int wid = tid >> 5;
    const int warpRow = wid >> 2;   // 0..1 -> 64 rows each
    const int warpCol = wid & 3;    // 0..3 -> 32 cols each
    const int blockM = blockIdx.y * BM;
    const int blockN = blockIdx.x * BN;

    const char* Ag[3] = {(const char*)A0, (const char*)A1, (const char*)A2};
    const char* Bg[3] = {(const char*)B0, (const char*)B1, (const char*)B2};
    constexpr size_t K2 = (size_t)KDIM * 2;

    // ---- stage loader: 6144 16B chunks, 24 per thread ----
    auto load_stage = [&](int bufb, int k0) {
        const uint32_t sbase = smem_u + bufb * STAGE_B;
        #pragma unroll
        for (int i = 0; i < 24; i++) {
            int L = tid + i * 256;
            int mc = L >> 10;         // 0..5: (comp<<1)|mat
            int c = L & 1023;
            int row = c >> 3, ch = c & 7;
            int comp = mc >> 1, mat = mc & 1;
            const char* g;
            if (mat == 0)
                g = Ag[comp] + (size_t)(blockM + row) * K2 + (size_t)k0 * 2 + ch * 16;
            else
                g = Bg[comp] + (size_t)(blockN + row) * K2 + (size_t)k0 * 2 + ch * 16;
            cp_async16(sbase + mc * TILE_B + row * STRIDE + ch * 16, g);
        }
        cp_commit();
    };

    float acc[4][4][4];   // main: hi*hi
    float acc2[4][4][4];  // corrections
    #pragma unroll
    for (int mt = 0; mt < 4; mt++)
        #pragma unroll
        for (int nt = 0; nt < 4; nt++)
            #pragma unroll
            for (int e = 0; e < 4; e++) { acc[mt][nt][e] = 0.0f; acc2[mt][nt][e] = 0.0f; }

    // ldmatrix per-lane address components
    const int rA = ((lane >> 3) & 1) * 8 + (lane & 7);
    const int cA = (lane >> 4);          // 0/1 -> 16B half of k16 slice
    const int rB = (lane >> 4) * 8 + (lane & 7);
    const int cB = (lane >> 3) & 1;

    // prologue: stage 0
    load_stage(0, 0);
    cp_wait0();
    __syncthreads();

    for (int it = 0; it < NITER; it++) {
        // issue next stage first (overwrites buffer consumed at it-1; safe:
        // barrier at end of it-1 has passed)
        if (it + 1 < NITER) load_stage((it + 1) & 1, (it + 1) * BK);

        const uint32_t stage = smem_u + (it & 1) * STAGE_B;
        #pragma unroll
        for (int kh = 0; kh < 4; kh++) {
            uint32_t aF[3][4][4];
            uint32_t bF[3][4][2];
            #pragma unroll
            for (int t = 0; t < 3; t++) {
                const uint32_t Abase = stage + (2 * t) * TILE_B;
                const uint32_t Bbase = stage + (2 * t + 1) * TILE_B;
                #pragma unroll
                for (int mt = 0; mt < 4; mt++) {
                    uint32_t addr = Abase + (warpRow * 64 + mt * 16 + rA) * STRIDE +
                                    (kh * 2 + cA) * 16;
                    ldmatrix_x4(aF[t][mt][0], aF[t][mt][1], aF[t][mt][2], aF[t][mt][3], addr);
                }
                #pragma unroll
                for (int pr = 0; pr < 2; pr++) {
                    uint32_t addr = Bbase + (warpCol * 32 + pr * 16 + rB) * STRIDE +
                                    (kh * 2 + cB) * 16;
                    uint32_t r0, r1, r2, r3;
                    ldmatrix_x4(r0, r1, r2, r3, addr);
                    bF[t][pr * 2 + 0][0] = r0; bF[t][pr * 2 + 0][1] = r1;
                    bF[t][pr * 2 + 1][0] = r2; bF[t][pr * 2 + 1][1] = r3;
                }
            }
            // main product -> acc
            #pragma unroll
            for (int mt = 0; mt < 4; mt++)
                #pragma unroll
                for (int nt = 0; nt < 4; nt++)
                    mma_bf16(acc[mt][nt], aF[0][mt], bF[0][nt]);
            // 5 correction products -> acc2
            const int pa[5] = {0, 1, 0, 1, 2};
            const int pb[5] = {1, 0, 2, 1, 0};
            #pragma unroll
            for (int p = 0; p < 5; p++) {
                #pragma unroll
                for (int mt = 0; mt < 4; mt++)
                    #pragma unroll
                    for (int nt = 0; nt < 4; nt++)
                        mma_bf16(acc2[mt][nt], aF[pa[p]][mt], bF[pb[p]][nt]);
            }
        }

        if (it + 1 < NITER) {
            cp_wait0();        // next stage data arrived (own thread)
            __syncthreads();   // cross-thread visibility + WAR protection
        }
    }

    // ---- epilogue ----
    const int gr = lane >> 2;         // row within 8
    const int cc = (lane & 3) * 2;    // col pair

    #pragma unroll
    for (int mt = 0; mt < 4; mt++) {
        #pragma unroll
        for (int nt = 0; nt < 4; nt++) {
            float d[4];
            #pragma unroll
            for (int e = 0; e < 4; e++) d[e] = acc[mt][nt][e] + acc2[mt][nt][e];
            const int col = blockN + warpCol * 32 + nt * 8 + cc;
            const int row0 = blockM + warpRow * 64 + mt * 16 + gr;
            float bv0, bv1;
            if (MODE == 0) {
                bv0 = bias[col];
                bv1 = bias[col + 1];
            } else {
                bv0 = (col < biasN) ? bias[col] : 0.0f;
                bv1 = (col + 1 < biasN) ? bias[col + 1] : 0.0f;
            }
            if (MODE == 0) {
                #pragma unroll
                for (int h = 0; h < 2; h++) {
                    const int row = row0 + h * 8;
                    float v0 = fmaxf(d[2 * h + 0] + bv0, 0.0f);
                    float v1 = fmaxf(d[2 * h + 1] + bv1, 0.0f);
                    __nv_bfloat16 h0, m0, l0, h1, m1, l1;
                    split3(v0, h0, m0, l0);
                    split3(v1, h1, m1, l1);
                    size_t off = (size_t)row * HIDDEN + col;
                    *(uint32_t*)(o_hi + off) = pack_bf16(h0, h1);
                    *(uint32_t*)(o_mi + off) = pack_bf16(m0, m1);
                    *(uint32_t*)(o_lo + off) = pack_bf16(l0, l1);
                }
            } else {
                #pragma unroll
                for (int h = 0; h < 2; h++) {
                    const int row = row0 + h * 8;
                    float2 v;
                    v.x = d[2 * h + 0] + bv0;
                    v.y = d[2 * h + 1] + bv1;
                    *(float2*)(o_f32 + (size_t)row * NPAD + col) = v;
                }
            }
        }
    }
}

// ---------------------------------------------------------------------------
// Row softmax (reads NPAD-strided logits, first CLASSES cols)
// ---------------------------------------------------------------------------
__inline__ __device__ float warpMax(float v) {
    #pragma unroll
    for (int o = 16; o > 0; o >>= 1) v = fmaxf(v, __shfl_xor_sync(0xffffffffu, v, o));
    return v;
}
__inline__ __device__ float warpSum(float v) {
    #pragma unroll
    for (int o = 16; o > 0; o >>= 1) v += __shfl_xor_sync(0xffffffffu, v, o);
    return v;
}

__global__ __launch_bounds__(256)
void softmax_kernel(const float* __restrict__ logits, float* __restrict__ out) {
    const int row = blockIdx.x;
    const float* lp = logits + (size_t)row * NPAD;
    float* op = out + (size_t)row * CLASSES;

    const int tid = threadIdx.x, lane = tid & 31, warp = tid >> 5;
    __shared__ float red[8];

    float v[4];
    int idx[4], cnt = 0;
    for (int i = tid; i < CLASSES; i += 256) { v[cnt] = lp[i]; idx[cnt] = i; cnt++; }

    float m = -INFINITY;
    for (int t = 0; t < cnt; t++) m = fmaxf(m, v[t]);
    m = warpMax(m);
    if (lane == 0) red[warp] = m;
    __syncthreads();
    m = (lane < 8) ? red[lane] : -INFINITY;
    m = warpMax(m);
    m = __shfl_sync(0xffffffffu, m, 0);

    float s = 0.0f;
    for (int t = 0; t < cnt; t++) { v[t] = __expf(v[t] - m); s += v[t]; }
    s = warpSum(s);
    __syncthreads();
    if (lane == 0) red[warp] = s;
    __syncthreads();
    s = (lane < 8) ? red[lane] : 0.0f;
    s = warpSum(s);
    s = __shfl_sync(0xffffffffu, s, 0);

    const float inv = 1.0f / s;
    for (int t = 0; t < cnt; t++) op[idx[t]] = v[t] * inv;
}

// ---------------------------------------------------------------------------
// Host launch
// ---------------------------------------------------------------------------
extern "C" void kernel_launch(void* const* d_in, const int* in_sizes, int n_in,
                              void* d_out, int out_size) {
    const float* x  = (const float*)d_in[0];
    const float* w1 = (const float*)d_in[1];
    const float* b1 = (const float*)d_in[2];
    const float* w2 = (const float*)d_in[3];
    const float* b2 = (const float*)d_in[4];
    float* out = (float*)d_out;

    __nv_bfloat16 *xs, *w1s, *w2s, *hs;
    float* logits;
    cudaGetSymbolAddress((void**)&xs,  g_x_s);
    cudaGetSymbolAddress((void**)&w1s, g_w1_s);
    cudaGetSymbolAddress((void**)&w2s, g_w2_s);
    cudaGetSymbolAddress((void**)&hs,  g_h_s);
    cudaGetSymbolAddress((void**)&logits, g_logits);

    const size_t XN  = (size_t)BATCH * INPUT;
    const size_t W1N = (size_t)HIDDEN * INPUT;
    const size_t W2N = (size_t)NPAD * INPUT;
    const size_t HN  = (size_t)BATCH * HIDDEN;

    __nv_bfloat16* x_c[3]  = {xs, xs + XN, xs + 2 * XN};
    __nv_bfloat16* w1_c[3] = {w1s, w1s + W1N, w1s + 2 * W1N};
    __nv_bfloat16* w2_c[3] = {w2s, w2s + W2N, w2s + 2 * W2N};
    __nv_bfloat16* h_c[3]  = {hs, hs + HN, hs + 2 * HN};

    {
        int n4 = (int)(XN / 4);
        split3_kernel<<<(n4 + 255) / 256, 256>>>((const float4*)x, n4, x_c[0], x_c[1], x_c[2]);
    }
    {
        int n4 = (int)(W1N / 4);
        split3_kernel<<<(n4 + 255) / 256, 256>>>((const float4*)w1, n4, w1_c[0], w1_c[1], w1_c[2]);
    }
    {
        int n4 = (int)(W2N / 4);
        split3_pad_kernel<<<(n4 + 255) / 256, 256>>>((const float4*)w2, n4, w2_c[0], w2_c[1], w2_c[2]);
    }

    cudaFuncSetAttribute(gemm_kernel<0>, cudaFuncAttributeMaxDynamicSharedMemorySize, DYN_SMEM);
    cudaFuncSetAttribute(gemm_kernel<1>, cudaFuncAttributeMaxDynamicSharedMemorySize, DYN_SMEM);

    // GEMM1: hidden = relu(x @ w1^T + b1), re-split into 3 bf16 components
    {
        dim3 grid(HIDDEN / BN, BATCH / BM);
        gemm_kernel<0><<<grid, 256, DYN_SMEM>>>(
            x_c[0], x_c[1], x_c[2], w1_c[0], w1_c[1], w1_c[2],
            b1, HIDDEN, h_c[0], h_c[1], h_c[2], nullptr);
    }
    // GEMM2: logits = hidden @ w2^T + b2 (fp32, NPAD-wide scratch)
    {
        dim3 grid(NPAD / BN, BATCH / BM);
        gemm_kernel<1><<<grid, 256, DYN_SMEM>>>(
            h_c[0], h_c[1], h_c[2], w2_c[0], w2_c[1], w2_c[2],
            b2, CLASSES, nullptr, nullptr, nullptr, logits);
    }
    softmax_kernel<<<BATCH, 256>>>(logits, out);
}